// round 14
// baseline (speedup 1.0000x reference)
#include <cuda_runtime.h>
#include <cuda_bf16.h>
#include <math.h>
#include <cstdint>

#define Ld    128
#define Dd    256
#define DEMOd 70
#define HIDd  1024
#define Nn    2048

// emb/T row stride: 264 halves = 528 B = 132 u32.  132 % 32 = 4 -> conflict-light.
#define RSTR32 132
#define RSTRH  264
#define ROWB   528

#define OFF_EMB   0
#define OFF_T     (128 * ROWB)            // 67584; scores f32 [128][132] alias
#define OFF_MC    (OFF_T + 128 * ROWB)    // 135168; probs bf16 [128][132] alias
#define OFF_TIMES (OFF_MC + 64 * ROWB)    // 168960
#define OFF_W     (OFF_TIMES + 512)
#define OFF_A     (OFF_W + 512)
#define OFF_U     (OFF_A + 512)
#define OFF_RED   (OFF_U + 1024)
#define OFF_CODES (OFF_RED + 2048)
#define SMEM_TOTAL (OFF_CODES + 512)      // 174,080 B -> 1 CTA/SM

#define SSCALE 0.0625f                    // 1/sqrt(D), folded into T

// device scratch
__device__ unsigned g_Mt[Dd * (Dd / 2)];  // Mt[n][k] = (WqWk^T)[k][n], bf16 [256][256]
__device__ float    g_repr[Nn * Dd];
__device__ float    g_part[2 * Nn];       // split-hidden partial logits

__device__ __forceinline__ unsigned pack2(float lo, float hi) {
    __nv_bfloat162 v; v.x = __float2bfloat16_rn(lo); v.y = __float2bfloat16_rn(hi);
    return *reinterpret_cast<const unsigned*>(&v);
}

// m16n8k16 bf16 HMMA (baseline PTX, sm_80+)
__device__ __forceinline__ void mma16816(float* c, unsigned a0, unsigned a1,
                                         unsigned a2, unsigned a3,
                                         unsigned b0, unsigned b1) {
    asm volatile(
        "mma.sync.aligned.m16n8k16.row.col.f32.bf16.bf16.f32 "
        "{%0,%1,%2,%3}, {%4,%5,%6,%7}, {%8,%9}, {%0,%1,%2,%3};"
        : "+f"(c[0]), "+f"(c[1]), "+f"(c[2]), "+f"(c[3])
        : "r"(a0), "r"(a1), "r"(a2), "r"(a3), "r"(b0), "r"(b1));
}
__device__ __forceinline__ void ldsm4(unsigned& r0, unsigned& r1, unsigned& r2,
                                      unsigned& r3, uint32_t addr) {
    asm volatile("ldmatrix.sync.aligned.m8n8.x4.shared.b16 {%0,%1,%2,%3}, [%4];"
                 : "=r"(r0), "=r"(r1), "=r"(r2), "=r"(r3) : "r"(addr));
}
__device__ __forceinline__ uint32_t smaddr(const void* p) {
    return (uint32_t)__cvta_generic_to_shared(p);
}

// ---------------------------------------------------------------------------
// Kernel 1: Mt[n][k] = sum_e Wq[k][e] * Wk[n][e]   (bf16 row-major [256][256])
// ---------------------------------------------------------------------------
__global__ void __launch_bounds__(256) k_M(const float* __restrict__ Wq,
                                           const float* __restrict__ Wk) {
    __shared__ float krow[Dd];
    int n = blockIdx.x;
    for (int e = threadIdx.x; e < Dd; e += 256) krow[e] = Wk[n * Dd + e];
    __syncthreads();
    int k = threadIdx.x;
    const float* q = Wq + k * Dd;
    float acc = 0.f;
#pragma unroll 8
    for (int e = 0; e < Dd; e++) acc += q[e] * krow[e];
    __nv_bfloat16 b = __float2bfloat16_rn(acc);
    ((unsigned short*)g_Mt)[n * Dd + k] = *reinterpret_cast<const unsigned short*>(&b);
}

// pad kernels: keep the ncu capture slot on k_main
__global__ void k_pad() {}

// ---------------------------------------------------------------------------
// Kernel 2: HMMA fused attention, fine-grained warp items. One CTA = one sample.
// ---------------------------------------------------------------------------
extern __shared__ char smem[];

__global__ void __launch_bounds__(512, 1) k_main(
    const float* __restrict__ E, const float* __restrict__ Wv,
    const float* __restrict__ c_attn, const float* __restrict__ c_pool,
    const float* __restrict__ hist_times, const float* __restrict__ event_time,
    const int* __restrict__ codes, const int* __restrict__ lengths)
{
    const int n    = blockIdx.x;
    const int tid  = threadIdx.x;
    const int wid  = tid >> 5;
    const int lane = tid & 31;
    const int g    = lane >> 2;
    const int t4   = lane & 3;
    const int len  = lengths[n];

    const int lrow = lane & 15;             // ldmatrix row within 16-row block
    const int lcol = (lane >> 4) * 16;      // 16B half-split

    unsigned* emb_u = (unsigned*)(smem + OFF_EMB);
    unsigned* t_u   = (unsigned*)(smem + OFF_T);
    unsigned* mc_u  = (unsigned*)(smem + OFF_MC);
    float*    times = (float*)(smem + OFF_TIMES);
    float*    w_sh  = (float*)(smem + OFF_W);
    float*    a_sh  = (float*)(smem + OFF_A);
    float*    u_sh  = (float*)(smem + OFF_U);
    float*    red_sh = (float*)(smem + OFF_RED);
    int*      codes_sh = (int*)(smem + OFF_CODES);

    if (tid < Ld) {
        codes_sh[tid] = codes[n * Ld + tid];
        times[tid]    = hist_times[n * Ld + tid];
    }
    __syncthreads();

    // ---- gather emb (all 128 rows) -> bf16 row-major [128][264]
    for (int idx = tid; idx < 128 * 32; idx += 512) {
        int l = idx >> 5, q = idx & 31;
        const float4* src = (const float4*)(E + (size_t)codes_sh[l] * Dd + q * 8);
        float4 f0 = src[0], f1 = src[1];
        uint4 o;
        o.x = pack2(f0.x, f0.y); o.y = pack2(f0.z, f0.w);
        o.z = pack2(f1.x, f1.y); o.w = pack2(f1.z, f1.w);
        *(uint4*)(emb_u + l * RSTR32 + q * 4) = o;
    }
    __syncthreads();

    const int nmt = (len + 15) >> 4;        // active 16-row m-tiles

    // ---- GEMM1: T = EMB @ M, T *= 1/sqrt(D).  Items = (mt, 16-col group).
    {
        const int nit1 = nmt * 4;
        for (int h = 0; h < 4; h++) {
            {
                const uint4* src = ((const uint4*)g_Mt) + h * 2048;
                for (int i = tid; i < 2048; i += 512) {
                    int r = i >> 5, c4 = i & 31;
                    *(uint4*)(mc_u + r * RSTR32 + c4 * 4) = src[i];
                }
            }
            __syncthreads();
            for (int it = wid; it < nit1; it += 16) {   // warp-uniform trip count
                const int mt = it >> 2, q = it & 3;
                const int m0 = mt * 16;
                const uint32_t aA = smaddr(emb_u + (m0 + lrow) * RSTR32) + lcol;
                const uint32_t aB = smaddr(mc_u + (q * 16 + lrow) * RSTR32) + lcol;
                float acc[8];
#pragma unroll
                for (int i = 0; i < 8; i++) acc[i] = 0.f;
#pragma unroll 4
                for (int kt = 0; kt < 16; kt++) {
                    unsigned a0, a1, a2, a3, p0, p1, p2, p3;
                    ldsm4(a0, a1, a2, a3, aA + kt * 32);
                    ldsm4(p0, p1, p2, p3, aB + kt * 32);
                    mma16816(acc + 0, a0, a1, a2, a3, p0, p2);
                    mma16816(acc + 4, a0, a1, a2, a3, p1, p3);
                }
#pragma unroll
                for (int nt = 0; nt < 2; nt++) {
                    int ncol = 32 * h + 8 * q + 4 * nt + t4;
                    t_u[(m0 + g) * RSTR32 + ncol] =
                        pack2(acc[4 * nt] * SSCALE, acc[4 * nt + 1] * SSCALE);
                    t_u[(m0 + g + 8) * RSTR32 + ncol] =
                        pack2(acc[4 * nt + 2] * SSCALE, acc[4 * nt + 3] * SSCALE);
                }
            }
            __syncthreads();
        }
    }

    // ---- GEMM2: S = T @ EMB^T.  Items = (mt, 16-col j group), 4 slots/warp.
    {
        const int njq = nmt;
        const int nit2 = nmt * njq;         // <= 64
        float acc2[4][8];
        int mts2[4], jqs2[4];
#pragma unroll
        for (int s = 0; s < 4; s++) {
            mts2[s] = -1;
            int it = wid + 16 * s;
            if (it < nit2) {
                int mt = it / njq, jq = it - mt * njq;
                mts2[s] = mt; jqs2[s] = jq;
                const int m0 = mt * 16;
                const uint32_t aA = smaddr(t_u + (m0 + lrow) * RSTR32) + lcol;
                const uint32_t aB = smaddr(emb_u + (jq * 16 + lrow) * RSTR32) + lcol;
#pragma unroll
                for (int i = 0; i < 8; i++) acc2[s][i] = 0.f;
#pragma unroll 4
                for (int kt = 0; kt < 16; kt++) {
                    unsigned a0, a1, a2, a3, p0, p1, p2, p3;
                    ldsm4(a0, a1, a2, a3, aA + kt * 32);
                    ldsm4(p0, p1, p2, p3, aB + kt * 32);
                    mma16816(acc2[s] + 0, a0, a1, a2, a3, p0, p2);
                    mma16816(acc2[s] + 4, a0, a1, a2, a3, p1, p3);
                }
            }
        }
        __syncthreads();                    // all reads of T done
        float* sc = (float*)(smem + OFF_T); // scores alias T, stride 132 f32
#pragma unroll
        for (int s = 0; s < 4; s++) {
            if (mts2[s] >= 0) {
                const int m0 = mts2[s] * 16;
#pragma unroll
                for (int jt = 0; jt < 2; jt++) {
                    int j = jqs2[s] * 16 + jt * 8 + 2 * t4;
                    *(float2*)(sc + (m0 + g) * RSTR32 + j) =
                        make_float2(acc2[s][4 * jt], acc2[s][4 * jt + 1]);
                    *(float2*)(sc + (m0 + g + 8) * RSTR32 + j) =
                        make_float2(acc2[s][4 * jt + 2], acc2[s][4 * jt + 3]);
                }
            }
        }
    }
    __syncthreads();

    // ---- softmax (no max-subtraction; |score| small) -> probs bf16 (alias MC)
    {
        const float ca = c_attn[0];
        const float* sc = (const float*)(smem + OFF_T);
        unsigned short* pp = (unsigned short*)(smem + OFF_MC);
        const int npass = (len + 63) >> 6;
        for (int p = 0; p < npass; p++) {
            const int r0 = p * 64 + wid * 4;
            if (r0 < len) {                 // warp-uniform
#pragma unroll
                for (int r = 0; r < 4; r++) {
                    int i = r0 + r;
                    if (i < len) {
                        float ti = times[i];
                        float ex[4]; float sum = 0.f;
#pragma unroll
                        for (int k = 0; k < 4; k++) {
                            ex[k] = 0.f;
                            if (32 * k < len) {         // warp-uniform
                                int j = 32 * k + lane;
                                if (j < len) {
                                    float sv = sc[i * RSTR32 + j]
                                             - ca * fabsf(ti - times[j]);
                                    ex[k] = __expf(sv);
                                }
                                sum += ex[k];
                            }
                        }
                        for (int o = 16; o; o >>= 1)
                            sum += __shfl_xor_sync(0xffffffffu, sum, o);
                        float inv = 1.f / sum;
#pragma unroll
                        for (int k = 0; k < 4; k++) {
                            if (32 * k < len) {
                                int j = 32 * k + lane;
                                __nv_bfloat16 b = __float2bfloat16_rn(ex[k] * inv);
                                if (j < len)
                                    pp[i * RSTR32 + j] =
                                        *reinterpret_cast<const unsigned short*>(&b);
                            }
                        }
                    }
                }
            }
        }
    }
    __syncthreads();

    // ---- phase 4: pooling -> a -> u -> repr
    {
        const float cp = c_pool[0];
        const float ev = event_time[n];
        if (tid < 32) {
            float s[4]; float mx = -1e30f;
#pragma unroll
            for (int k = 0; k < 4; k++) {
                int l = lane + 32 * k;
                s[k] = (l < len) ? -cp * (ev - times[l]) : -1e30f;
                mx = fmaxf(mx, s[k]);
            }
            for (int o = 16; o; o >>= 1) mx = fmaxf(mx, __shfl_xor_sync(0xffffffffu, mx, o));
            float ex[4]; float sum = 0.f;
#pragma unroll
            for (int k = 0; k < 4; k++) {
                int l = lane + 32 * k;
                ex[k] = (l < len) ? __expf(s[k] - mx) : 0.f;
                sum += ex[k];
            }
            for (int o = 16; o; o >>= 1) sum += __shfl_xor_sync(0xffffffffu, sum, o);
            float inv = 1.f / sum;
#pragma unroll
            for (int k = 0; k < 4; k++) {
                int l = lane + 32 * k;
                if (l < Ld) w_sh[l] = (l < len) ? ex[k] * inv : 0.f;
            }
        }
        __syncthreads();

        if (tid < 128) {                    // a_j = sum_l w_l * probs[l][j]
            int j = tid;
            float a = 0.f;
            if (j < len) {
                const unsigned short* pp = (const unsigned short*)(smem + OFF_MC);
                for (int l = 0; l < len; l++)
                    a += w_sh[l] * __bfloat162float(__ushort_as_bfloat16(pp[l * RSTR32 + j]));
            }
            a_sh[j] = (j < len) ? a : 0.f;
        }
        __syncthreads();

        if (tid < 256) {                    // u_d = sum_j a_j * emb[j][d]
            int d = tid;
            float u = 0.f;
            const unsigned short* eh = (const unsigned short*)(smem + OFF_EMB);
            for (int j = 0; j < len; j++)
                u += a_sh[j] * __bfloat162float(__ushort_as_bfloat16(eh[j * RSTRH + d]));
            u_sh[d] = u;
        }
        __syncthreads();

        {   // repr[e] = sum_d u_d * Wv[d][e]
            int e = tid & 255, h = tid >> 8;
            float r = 0.f;
            const float* wv = Wv + (h * 128) * Dd + e;
#pragma unroll 4
            for (int d = 0; d < 128; d++) r += u_sh[h * 128 + d] * wv[d * Dd];
            red_sh[tid] = r;
        }
        __syncthreads();
        if (tid < 256)
            g_repr[n * Dd + tid] = red_sh[tid] + red_sh[tid + 256];
    }
}

// ---------------------------------------------------------------------------
// Kernel 3: MLP split over hidden dim. grid=(128,2); CTA y owns hidden
// [512y, 512y+512); partial logit -> g_part[y][n].
// ---------------------------------------------------------------------------
#define TILE 16
#define XF   (DEMOd + Dd)

__global__ void __launch_bounds__(512) k_mlp(
    const float* __restrict__ W1, const float* __restrict__ b1,
    const float* __restrict__ W2,
    const float* __restrict__ demo)
{
    __shared__ float x_s[XF * TILE];
    __shared__ float red[16 * TILE];
    const int n0 = blockIdx.x * TILE, tid = threadIdx.x;
    const int y = blockIdx.y;
    const int hid = y * 512 + tid;
    const int wid = tid >> 5, lane = tid & 31;

    for (int idx = tid; idx < XF * TILE; idx += 512) {
        int m = idx >> 4, s = idx & 15;
        x_s[idx] = (m < DEMOd) ? demo[(n0 + s) * DEMOd + m]
                               : g_repr[(n0 + s) * Dd + (m - DEMOd)];
    }
    __syncthreads();

    float h[TILE];
    {
        float b = b1[hid];
#pragma unroll
        for (int s = 0; s < TILE; s++) h[s] = b;
    }
#pragma unroll 2
    for (int m = 0; m < XF; m++) {
        float w1 = W1[m * HIDd + hid];
        float4 x0 = ((const float4*)(x_s + m * TILE))[0];
        float4 x1 = ((const float4*)(x_s + m * TILE))[1];
        float4 x2 = ((const float4*)(x_s + m * TILE))[2];
        float4 x3 = ((const float4*)(x_s + m * TILE))[3];
        float xv[TILE] = {x0.x, x0.y, x0.z, x0.w, x1.x, x1.y, x1.z, x1.w,
                          x2.x, x2.y, x2.z, x2.w, x3.x, x3.y, x3.z, x3.w};
#pragma unroll
        for (int s = 0; s < TILE; s++) h[s] += w1 * xv[s];
    }

    float part[TILE];
    {
        float w2 = W2[hid];
#pragma unroll
        for (int s = 0; s < TILE; s++) part[s] = fmaxf(h[s], 0.f) * w2;
    }
#pragma unroll
    for (int s = 0; s < TILE; s++)
        for (int o = 16; o; o >>= 1)
            part[s] += __shfl_xor_sync(0xffffffffu, part[s], o);
    if (lane == 0)
#pragma unroll
        for (int s = 0; s < TILE; s++) red[wid * TILE + s] = part[s];
    __syncthreads();
    if (tid < TILE) {
        float z = 0.f;
#pragma unroll
        for (int w = 0; w < 16; w++) z += red[w * TILE + tid];
        g_part[y * Nn + n0 + tid] = z;
    }
}

// ---------------------------------------------------------------------------
// Kernel 4: BCE + deterministic reduce + regularization
// ---------------------------------------------------------------------------
__device__ __forceinline__ float log_sigmoid(float z) {
    return (z >= 0.f) ? -log1pf(expf(-z)) : z - log1pf(expf(z));
}

__global__ void __launch_bounds__(256) k_red(const float* __restrict__ c_attn,
                                             const float* __restrict__ c_pool,
                                             const float* __restrict__ b2,
                                             const float* __restrict__ labels,
                                             float* __restrict__ out)
{
    __shared__ float red[256];
    int tid = threadIdx.x;
    float s = 0.f;
    float bb = b2[0];
    for (int i = tid; i < Nn; i += 256) {
        float z = g_part[i] + g_part[Nn + i] + bb;
        float y = labels[i];
        s += -(2.0f * y * log_sigmoid(z) + (1.0f - y) * log_sigmoid(-z));
    }
    red[tid] = s;
    __syncthreads();
    for (int k = 128; k > 0; k >>= 1) {
        if (tid < k) red[tid] += red[tid + k];
        __syncthreads();
    }
    if (tid == 0)
        out[0] = red[0] / (float)Nn + c_attn[0] * c_attn[0] + c_pool[0] * c_pool[0];
}

// ---------------------------------------------------------------------------
extern "C" void kernel_launch(void* const* d_in, const int* in_sizes, int n_in,
                              void* d_out, int out_size)
{
    const float* E          = (const float*)d_in[0];
    const float* Wq         = (const float*)d_in[1];
    const float* Wk         = (const float*)d_in[2];
    const float* Wv         = (const float*)d_in[3];
    const float* c_attn     = (const float*)d_in[4];
    const float* c_pool     = (const float*)d_in[5];
    const float* W1         = (const float*)d_in[6];
    const float* b1         = (const float*)d_in[7];
    const float* W2         = (const float*)d_in[8];
    const float* b2         = (const float*)d_in[9];
    const float* demo       = (const float*)d_in[10];
    const float* hist_times = (const float*)d_in[11];
    const float* event_time = (const float*)d_in[12];
    const float* labels     = (const float*)d_in[13];
    const int*   codes      = (const int*)d_in[14];
    const int*   lengths    = (const int*)d_in[15];

    cudaFuncSetAttribute(k_main, cudaFuncAttributeMaxDynamicSharedMemorySize, SMEM_TOTAL);

    k_M   <<<Dd, 256>>>(Wq, Wk);
    k_pad <<<1, 32>>>();
    k_pad <<<1, 32>>>();
    k_main<<<Nn, 512, SMEM_TOTAL>>>(E, Wv, c_attn, c_pool, hist_times, event_time,
                                    codes, lengths);
    k_mlp <<<dim3(Nn / TILE, 2), 512>>>(W1, b1, W2, demo);
    k_red <<<1, 256>>>(c_attn, c_pool, b2, labels, (float*)d_out);
}

// round 15
// speedup vs baseline: 1.2096x; 1.2096x over previous
#include <cuda_runtime.h>
#include <cuda_bf16.h>
#include <math.h>
#include <cstdint>

#define Ld    128
#define Dd    256
#define DEMOd 70
#define HIDd  1024
#define Nn    2048

// emb row stride: 264 halves = 528 B (16B-aligned, 33*16B odd -> ldsm conflict-free)
#define ESTRB  528
#define ESTR32 132
#define ESTRH  264
// T-chunk row stride: 40 halves = 80 B (5*16B odd -> conflict-free)
#define TSTRB  80
#define TSTR32 20
// scores/probs row stride: 132 halves (66 u32)
#define PSTRH  132
#define PSTR32 66

#define OFF_EMB   0                       // 67584 B
#define OFF_RGN   67584                   // region: Mchunk+Tchunk | S/probs bf16
#define OFF_MCH   OFF_RGN                 // 16896 B (32 x 528)
#define OFF_TCH   (OFF_RGN + 16896)       // 10240 B (128 x 80)
#define OFF_TIMES (OFF_RGN + 33792)       // region size 33792 (128 x 264)
#define OFF_W     (OFF_TIMES + 512)
#define OFF_A     (OFF_W + 512)
#define OFF_U     (OFF_A + 512)
#define OFF_RED   (OFF_U + 1024)
#define OFF_CODES (OFF_RED + 2048)
#define SMEM_TOTAL (OFF_CODES + 512)      // 106,496 B -> 2 CTAs/SM

#define SSCALE 0.0625f                    // 1/sqrt(D), folded into T

// device scratch
__device__ unsigned g_Mt[Dd * (Dd / 2)];  // Mt[n][k] = (WqWk^T)[k][n], bf16 [256][256]
__device__ float    g_repr[Nn * Dd];
__device__ float    g_part[2 * Nn];       // split-hidden partial logits

__device__ __forceinline__ unsigned pack2(float lo, float hi) {
    __nv_bfloat162 v; v.x = __float2bfloat16_rn(lo); v.y = __float2bfloat16_rn(hi);
    return *reinterpret_cast<const unsigned*>(&v);
}
__device__ __forceinline__ void mma16816(float* c, unsigned a0, unsigned a1,
                                         unsigned a2, unsigned a3,
                                         unsigned b0, unsigned b1) {
    asm volatile(
        "mma.sync.aligned.m16n8k16.row.col.f32.bf16.bf16.f32 "
        "{%0,%1,%2,%3}, {%4,%5,%6,%7}, {%8,%9}, {%0,%1,%2,%3};"
        : "+f"(c[0]), "+f"(c[1]), "+f"(c[2]), "+f"(c[3])
        : "r"(a0), "r"(a1), "r"(a2), "r"(a3), "r"(b0), "r"(b1));
}
__device__ __forceinline__ void ldsm4(unsigned& r0, unsigned& r1, unsigned& r2,
                                      unsigned& r3, uint32_t addr) {
    asm volatile("ldmatrix.sync.aligned.m8n8.x4.shared.b16 {%0,%1,%2,%3}, [%4];"
                 : "=r"(r0), "=r"(r1), "=r"(r2), "=r"(r3) : "r"(addr));
}
__device__ __forceinline__ uint32_t smaddr(const void* p) {
    return (uint32_t)__cvta_generic_to_shared(p);
}

// ---------------------------------------------------------------------------
// Kernel 1: Mt[n][k] = sum_e Wq[k][e] * Wk[n][e]   (bf16 row-major [256][256])
// ---------------------------------------------------------------------------
__global__ void __launch_bounds__(256) k_M(const float* __restrict__ Wq,
                                           const float* __restrict__ Wk) {
    __shared__ float krow[Dd];
    int n = blockIdx.x;
    for (int e = threadIdx.x; e < Dd; e += 256) krow[e] = Wk[n * Dd + e];
    __syncthreads();
    int k = threadIdx.x;
    const float* q = Wq + k * Dd;
    float acc = 0.f;
#pragma unroll 8
    for (int e = 0; e < Dd; e++) acc += q[e] * krow[e];
    __nv_bfloat16 b = __float2bfloat16_rn(acc);
    ((unsigned short*)g_Mt)[n * Dd + k] = *reinterpret_cast<const unsigned short*>(&b);
}

// pad kernels: keep the ncu capture slot on k_main
__global__ void k_pad() {}

// ---------------------------------------------------------------------------
// Kernel 2: HMMA fused attention, d'-chunked, S in registers. 2 CTAs/SM.
// ---------------------------------------------------------------------------
extern __shared__ char smem[];

__global__ void __launch_bounds__(512, 2) k_main(
    const float* __restrict__ E, const float* __restrict__ Wv,
    const float* __restrict__ c_attn, const float* __restrict__ c_pool,
    const float* __restrict__ hist_times, const float* __restrict__ event_time,
    const int* __restrict__ codes, const int* __restrict__ lengths)
{
    const int n    = blockIdx.x;
    const int tid  = threadIdx.x;
    const int wid  = tid >> 5;
    const int lane = tid & 31;
    const int g    = lane >> 2;
    const int t4   = lane & 3;
    const int len  = lengths[n];

    const int lrow = lane & 15;
    const int lcol = (lane >> 4) * 16;

    unsigned* emb_u = (unsigned*)(smem + OFF_EMB);
    unsigned* mch_u = (unsigned*)(smem + OFF_MCH);
    unsigned* tch_u = (unsigned*)(smem + OFF_TCH);
    float*    times = (float*)(smem + OFF_TIMES);
    float*    w_sh  = (float*)(smem + OFF_W);
    float*    a_sh  = (float*)(smem + OFF_A);
    float*    u_sh  = (float*)(smem + OFF_U);
    float*    red_sh = (float*)(smem + OFF_RED);
    int*      codes_sh = (int*)(smem + OFF_CODES);

    if (tid < Ld) {
        codes_sh[tid] = codes[n * Ld + tid];
        times[tid]    = hist_times[n * Ld + tid];
    }
    __syncthreads();

    // ---- gather emb (all 128 rows) -> bf16 row-major [128][264]
    for (int idx = tid; idx < 128 * 32; idx += 512) {
        int l = idx >> 5, q = idx & 31;
        const float4* src = (const float4*)(E + (size_t)codes_sh[l] * Dd + q * 8);
        float4 f0 = src[0], f1 = src[1];
        uint4 o;
        o.x = pack2(f0.x, f0.y); o.y = pack2(f0.z, f0.w);
        o.z = pack2(f1.x, f1.y); o.w = pack2(f1.z, f1.w);
        *(uint4*)(emb_u + l * ESTR32 + q * 4) = o;
    }
    __syncthreads();

    const int nmt = (len + 15) >> 4;        // active 16-row m-tiles
    const int njq = (len + 31) >> 5;        // 32-col j groups
    const int nit2 = nmt * njq;             // <= 32

    // static GEMM2 slot assignment (2 slots/warp)
    float acc2[2][16];
    int mts2[2], jqs2[2];
#pragma unroll
    for (int s = 0; s < 2; s++) {
        mts2[s] = -1;
        int it = wid + 16 * s;
        if (it < nit2) {
            mts2[s] = (it / njq) * 16;
            jqs2[s] = it - (it / njq) * njq;
#pragma unroll
            for (int i = 0; i < 16; i++) acc2[s][i] = 0.f;
        }
    }

    const int nit1 = nmt * 2;

    // ---- d'-chunk loop: GEMM1 slice -> T-chunk -> GEMM2 accumulate
    for (int h = 0; h < 8; h++) {
        // stage Mchunk: Mt rows [32h, 32h+32), all 256 k
        {
            const uint4* src = ((const uint4*)g_Mt) + h * 1024;
            for (int i = tid; i < 1024; i += 512) {
                int r = i >> 5, c4 = i & 31;
                *(uint4*)(mch_u + r * ESTR32 + c4 * 4) = src[i];
            }
        }
        __syncthreads();

        // GEMM1: Tchunk[0:128][0:32] = EMB @ Mt[32h..]^T, scaled
        for (int it = wid; it < nit1; it += 16) {
            const int m0 = (it >> 1) * 16, ng = it & 1;
            const uint32_t aA = smaddr(emb_u) + (m0 + lrow) * ESTRB + lcol;
            const uint32_t aB = smaddr(mch_u) + (ng * 16 + lrow) * ESTRB + lcol;
            float acc[8];
#pragma unroll
            for (int i = 0; i < 8; i++) acc[i] = 0.f;
#pragma unroll 4
            for (int kt = 0; kt < 16; kt++) {
                unsigned a0, a1, a2, a3, p0, p1, p2, p3;
                ldsm4(a0, a1, a2, a3, aA + kt * 32);
                ldsm4(p0, p1, p2, p3, aB + kt * 32);
                mma16816(acc + 0, a0, a1, a2, a3, p0, p2);
                mma16816(acc + 4, a0, a1, a2, a3, p1, p3);
            }
#pragma unroll
            for (int nt = 0; nt < 2; nt++) {
                int col = ng * 8 + nt * 4 + t4;
                tch_u[(m0 + g) * TSTR32 + col] =
                    pack2(acc[4 * nt] * SSCALE, acc[4 * nt + 1] * SSCALE);
                tch_u[(m0 + g + 8) * TSTR32 + col] =
                    pack2(acc[4 * nt + 2] * SSCALE, acc[4 * nt + 3] * SSCALE);
            }
        }
        __syncthreads();

        // GEMM2: S += Tchunk @ emb[:, 32h:32h+32]^T
#pragma unroll
        for (int s = 0; s < 2; s++) {
            if (mts2[s] >= 0) {
                const uint32_t aA2 = smaddr(tch_u) + (mts2[s] + lrow) * TSTRB + lcol;
                const uint32_t eb  = smaddr(emb_u) + h * 64 + lcol;
#pragma unroll
                for (int kt2 = 0; kt2 < 2; kt2++) {
                    unsigned a0, a1, a2, a3;
                    ldsm4(a0, a1, a2, a3, aA2 + kt2 * 32);
#pragma unroll
                    for (int jg = 0; jg < 2; jg++) {
                        unsigned p0, p1, p2, p3;
                        ldsm4(p0, p1, p2, p3,
                              eb + (jqs2[s] * 32 + jg * 16 + lrow) * ESTRB + kt2 * 32);
                        mma16816(acc2[s] + 8 * jg + 0, a0, a1, a2, a3, p0, p2);
                        mma16816(acc2[s] + 8 * jg + 4, a0, a1, a2, a3, p1, p3);
                    }
                }
            }
        }
        __syncthreads();
    }

    // ---- write S (bf16) into region (Mchunk/Tchunk now dead)
    {
        unsigned* pp32 = (unsigned*)(smem + OFF_RGN);
#pragma unroll
        for (int s = 0; s < 2; s++) {
            if (mts2[s] >= 0) {
                const int m0 = mts2[s];
#pragma unroll
                for (int jt = 0; jt < 4; jt++) {
                    int col = jqs2[s] * 16 + jt * 4 + t4;
                    pp32[(m0 + g) * PSTR32 + col] =
                        pack2(acc2[s][4 * jt], acc2[s][4 * jt + 1]);
                    pp32[(m0 + g + 8) * PSTR32 + col] =
                        pack2(acc2[s][4 * jt + 2], acc2[s][4 * jt + 3]);
                }
            }
        }
    }
    __syncthreads();

    // ---- softmax in place (bf16 scores -> bf16 probs); no max-subtraction
    {
        const float ca = c_attn[0];
        unsigned short* pp = (unsigned short*)(smem + OFF_RGN);
        const int npass = (len + 63) >> 6;
        for (int p = 0; p < npass; p++) {
            const int r0 = p * 64 + wid * 4;
            if (r0 < len) {                 // warp-uniform
#pragma unroll
                for (int r = 0; r < 4; r++) {
                    int i = r0 + r;
                    if (i < len) {
                        float ti = times[i];
                        float ex[4]; float sum = 0.f;
#pragma unroll
                        for (int k = 0; k < 4; k++) {
                            ex[k] = 0.f;
                            if (32 * k < len) {         // warp-uniform
                                int j = 32 * k + lane;
                                if (j < len) {
                                    float sv = __bfloat162float(__ushort_as_bfloat16(
                                                   pp[i * PSTRH + j]))
                                             - ca * fabsf(ti - times[j]);
                                    ex[k] = __expf(sv);
                                }
                                sum += ex[k];
                            }
                        }
                        for (int o = 16; o; o >>= 1)
                            sum += __shfl_xor_sync(0xffffffffu, sum, o);
                        float inv = 1.f / sum;
#pragma unroll
                        for (int k = 0; k < 4; k++) {
                            if (32 * k < len) {
                                int j = 32 * k + lane;
                                __nv_bfloat16 b = __float2bfloat16_rn(ex[k] * inv);
                                if (j < len)
                                    pp[i * PSTRH + j] =
                                        *reinterpret_cast<const unsigned short*>(&b);
                            }
                        }
                    }
                }
            }
        }
    }
    __syncthreads();

    // ---- phase 4: pooling -> a -> u -> repr
    {
        const float cp = c_pool[0];
        const float ev = event_time[n];
        if (tid < 32) {
            float s[4]; float mx = -1e30f;
#pragma unroll
            for (int k = 0; k < 4; k++) {
                int l = lane + 32 * k;
                s[k] = (l < len) ? -cp * (ev - times[l]) : -1e30f;
                mx = fmaxf(mx, s[k]);
            }
            for (int o = 16; o; o >>= 1) mx = fmaxf(mx, __shfl_xor_sync(0xffffffffu, mx, o));
            float ex[4]; float sum = 0.f;
#pragma unroll
            for (int k = 0; k < 4; k++) {
                int l = lane + 32 * k;
                ex[k] = (l < len) ? __expf(s[k] - mx) : 0.f;
                sum += ex[k];
            }
            for (int o = 16; o; o >>= 1) sum += __shfl_xor_sync(0xffffffffu, sum, o);
            float inv = 1.f / sum;
#pragma unroll
            for (int k = 0; k < 4; k++) {
                int l = lane + 32 * k;
                if (l < Ld) w_sh[l] = (l < len) ? ex[k] * inv : 0.f;
            }
        }
        __syncthreads();

        if (tid < 128) {                    // a_j = sum_l w_l * probs[l][j]
            int j = tid;
            float a = 0.f;
            if (j < len) {
                const unsigned short* pp = (const unsigned short*)(smem + OFF_RGN);
                for (int l = 0; l < len; l++)
                    a += w_sh[l] * __bfloat162float(__ushort_as_bfloat16(pp[l * PSTRH + j]));
            }
            a_sh[j] = (j < len) ? a : 0.f;
        }
        __syncthreads();

        if (tid < 256) {                    // u_d = sum_j a_j * emb[j][d]
            int d = tid;
            float u = 0.f;
            const unsigned short* eh = (const unsigned short*)(smem + OFF_EMB);
            for (int j = 0; j < len; j++)
                u += a_sh[j] * __bfloat162float(__ushort_as_bfloat16(eh[j * ESTRH + d]));
            u_sh[d] = u;
        }
        __syncthreads();

        {   // repr[e] = sum_d u_d * Wv[d][e]
            int e = tid & 255, h2 = tid >> 8;
            float r = 0.f;
            const float* wv = Wv + (h2 * 128) * Dd + e;
#pragma unroll 4
            for (int d = 0; d < 128; d++) r += u_sh[h2 * 128 + d] * wv[d * Dd];
            red_sh[tid] = r;
        }
        __syncthreads();
        if (tid < 256)
            g_repr[n * Dd + tid] = red_sh[tid] + red_sh[tid + 256];
    }
}

// ---------------------------------------------------------------------------
// Kernel 3: MLP split over hidden dim. grid=(128,2); partial -> g_part[y][n].
// ---------------------------------------------------------------------------
#define TILE 16
#define XF   (DEMOd + Dd)

__global__ void __launch_bounds__(512) k_mlp(
    const float* __restrict__ W1, const float* __restrict__ b1,
    const float* __restrict__ W2,
    const float* __restrict__ demo)
{
    __shared__ float x_s[XF * TILE];
    __shared__ float red[16 * TILE];
    const int n0 = blockIdx.x * TILE, tid = threadIdx.x;
    const int y = blockIdx.y;
    const int hid = y * 512 + tid;
    const int wid = tid >> 5, lane = tid & 31;

    for (int idx = tid; idx < XF * TILE; idx += 512) {
        int m = idx >> 4, s = idx & 15;
        x_s[idx] = (m < DEMOd) ? demo[(n0 + s) * DEMOd + m]
                               : g_repr[(n0 + s) * Dd + (m - DEMOd)];
    }
    __syncthreads();

    float h[TILE];
    {
        float b = b1[hid];
#pragma unroll
        for (int s = 0; s < TILE; s++) h[s] = b;
    }
#pragma unroll 2
    for (int m = 0; m < XF; m++) {
        float w1 = W1[m * HIDd + hid];
        float4 x0 = ((const float4*)(x_s + m * TILE))[0];
        float4 x1 = ((const float4*)(x_s + m * TILE))[1];
        float4 x2 = ((const float4*)(x_s + m * TILE))[2];
        float4 x3 = ((const float4*)(x_s + m * TILE))[3];
        float xv[TILE] = {x0.x, x0.y, x0.z, x0.w, x1.x, x1.y, x1.z, x1.w,
                          x2.x, x2.y, x2.z, x2.w, x3.x, x3.y, x3.z, x3.w};
#pragma unroll
        for (int s = 0; s < TILE; s++) h[s] += w1 * xv[s];
    }

    float part[TILE];
    {
        float w2 = W2[hid];
#pragma unroll
        for (int s = 0; s < TILE; s++) part[s] = fmaxf(h[s], 0.f) * w2;
    }
#pragma unroll
    for (int s = 0; s < TILE; s++)
        for (int o = 16; o; o >>= 1)
            part[s] += __shfl_xor_sync(0xffffffffu, part[s], o);
    if (lane == 0)
#pragma unroll
        for (int s = 0; s < TILE; s++) red[wid * TILE + s] = part[s];
    __syncthreads();
    if (tid < TILE) {
        float z = 0.f;
#pragma unroll
        for (int w = 0; w < 16; w++) z += red[w * TILE + tid];
        g_part[y * Nn + n0 + tid] = z;
    }
}

// ---------------------------------------------------------------------------
// Kernel 4: BCE + deterministic reduce + regularization
// ---------------------------------------------------------------------------
__device__ __forceinline__ float log_sigmoid(float z) {
    return (z >= 0.f) ? -log1pf(expf(-z)) : z - log1pf(expf(z));
}

__global__ void __launch_bounds__(256) k_red(const float* __restrict__ c_attn,
                                             const float* __restrict__ c_pool,
                                             const float* __restrict__ b2,
                                             const float* __restrict__ labels,
                                             float* __restrict__ out)
{
    __shared__ float red[256];
    int tid = threadIdx.x;
    float s = 0.f;
    float bb = b2[0];
    for (int i = tid; i < Nn; i += 256) {
        float z = g_part[i] + g_part[Nn + i] + bb;
        float y = labels[i];
        s += -(2.0f * y * log_sigmoid(z) + (1.0f - y) * log_sigmoid(-z));
    }
    red[tid] = s;
    __syncthreads();
    for (int k = 128; k > 0; k >>= 1) {
        if (tid < k) red[tid] += red[tid + k];
        __syncthreads();
    }
    if (tid == 0)
        out[0] = red[0] / (float)Nn + c_attn[0] * c_attn[0] + c_pool[0] * c_pool[0];
}

// ---------------------------------------------------------------------------
extern "C" void kernel_launch(void* const* d_in, const int* in_sizes, int n_in,
                              void* d_out, int out_size)
{
    const float* E          = (const float*)d_in[0];
    const float* Wq         = (const float*)d_in[1];
    const float* Wk         = (const float*)d_in[2];
    const float* Wv         = (const float*)d_in[3];
    const float* c_attn     = (const float*)d_in[4];
    const float* c_pool     = (const float*)d_in[5];
    const float* W1         = (const float*)d_in[6];
    const float* b1         = (const float*)d_in[7];
    const float* W2         = (const float*)d_in[8];
    const float* b2         = (const float*)d_in[9];
    const float* demo       = (const float*)d_in[10];
    const float* hist_times = (const float*)d_in[11];
    const float* event_time = (const float*)d_in[12];
    const float* labels     = (const float*)d_in[13];
    const int*   codes      = (const int*)d_in[14];
    const int*   lengths    = (const int*)d_in[15];

    cudaFuncSetAttribute(k_main, cudaFuncAttributeMaxDynamicSharedMemorySize, SMEM_TOTAL);

    k_M   <<<Dd, 256>>>(Wq, Wk);
    k_pad <<<1, 32>>>();
    k_pad <<<1, 32>>>();
    k_main<<<Nn, 512, SMEM_TOTAL>>>(E, Wv, c_attn, c_pool, hist_times, event_time,
                                    codes, lengths);
    k_mlp <<<dim3(Nn / TILE, 2), 512>>>(W1, b1, W2, demo);
    k_red <<<1, 256>>>(c_attn, c_pool, b2, labels, (float*)d_out);
}

// round 16
// speedup vs baseline: 1.2977x; 1.0728x over previous
#include <cuda_runtime.h>
#include <cuda_bf16.h>
#include <cuda_fp16.h>
#include <math.h>
#include <cstdint>

#define Ld    128
#define Dd    256
#define DEMOd 70
#define HIDd  1024
#define Nn    2048

// emb row stride: 264 halves = 528 B (33*16B odd -> ldsm conflict-free)
#define ESTRB  528
#define ESTR32 132
#define ESTRH  264
// T-chunk row stride: 40 halves = 80 B
#define TSTRB  80
#define TSTR32 20
// scores/probs row stride: 132 halves (66 u32)
#define PSTRH  132
#define PSTR32 66

#define OFF_EMB   0                       // 67584 B
#define OFF_RGN   67584                   // region: Mchunk+Tchunk | S/probs bf16
#define OFF_MCH   OFF_RGN                 // 16896 B (32 x 528)
#define OFF_TCH   (OFF_RGN + 16896)       // 10240 B (128 x 80)
#define OFF_TIMES (OFF_RGN + 33792)
#define OFF_W     (OFF_TIMES + 512)
#define OFF_A     (OFF_W + 512)
#define OFF_RED   (OFF_A + 512)
#define OFF_CODES (OFF_RED + 2048)
#define SMEM_TOTAL (OFF_CODES + 512)      // 105,984 B -> 2 CTAs/SM

// 1/sqrt(D) * log2(e): scores live in the log2 domain (ex2-ready)
#define SSCALE (0.0625f * 1.44269504f)

// device scratch
__device__ unsigned g_Mt[Dd * (Dd / 2)];  // Mt[n][k] = (WqWk^T)[k][n], bf16 [256][256]
__device__ float    g_repr[Nn * Dd];      // holds u (pre-Wv pooled vector)
__device__ float    g_part[2 * Nn];       // split-hidden partial logits
__device__ float    g_W1f[(DEMOd + Dd) * HIDd];   // folded W1: [W1_demo; Wv@W1_hist]

__device__ __forceinline__ unsigned pack2(float lo, float hi) {
    __nv_bfloat162 v; v.x = __float2bfloat16_rn(lo); v.y = __float2bfloat16_rn(hi);
    return *reinterpret_cast<const unsigned*>(&v);
}
__device__ __forceinline__ float bf2f(unsigned short u) {
    return __bfloat162float(__ushort_as_bfloat16(u));
}
__device__ __forceinline__ float2 exp2_pair(float a, float b) {
    __half2 h = __floats2half2_rn(a, b);
    unsigned hx = *reinterpret_cast<unsigned*>(&h), hr;
    asm("ex2.approx.f16x2 %0, %1;" : "=r"(hr) : "r"(hx));
    __half2 h2 = *reinterpret_cast<__half2*>(&hr);
    return __half22float2(h2);
}
__device__ __forceinline__ void mma16816(float* c, unsigned a0, unsigned a1,
                                         unsigned a2, unsigned a3,
                                         unsigned b0, unsigned b1) {
    asm volatile(
        "mma.sync.aligned.m16n8k16.row.col.f32.bf16.bf16.f32 "
        "{%0,%1,%2,%3}, {%4,%5,%6,%7}, {%8,%9}, {%0,%1,%2,%3};"
        : "+f"(c[0]), "+f"(c[1]), "+f"(c[2]), "+f"(c[3])
        : "r"(a0), "r"(a1), "r"(a2), "r"(a3), "r"(b0), "r"(b1));
}
__device__ __forceinline__ void ldsm4(unsigned& r0, unsigned& r1, unsigned& r2,
                                      unsigned& r3, uint32_t addr) {
    asm volatile("ldmatrix.sync.aligned.m8n8.x4.shared.b16 {%0,%1,%2,%3}, [%4];"
                 : "=r"(r0), "=r"(r1), "=r"(r2), "=r"(r3) : "r"(addr));
}
__device__ __forceinline__ uint32_t smaddr(const void* p) {
    return (uint32_t)__cvta_generic_to_shared(p);
}

// ---------------------------------------------------------------------------
// Kernel 1: Mt[n][k] = sum_e Wq[k][e] * Wk[n][e]   (bf16 row-major [256][256])
// ---------------------------------------------------------------------------
__global__ void __launch_bounds__(256) k_M(const float* __restrict__ Wq,
                                           const float* __restrict__ Wk) {
    __shared__ float krow[Dd];
    int n = blockIdx.x;
    for (int e = threadIdx.x; e < Dd; e += 256) krow[e] = Wk[n * Dd + e];
    __syncthreads();
    int k = threadIdx.x;
    const float* q = Wq + k * Dd;
    float acc = 0.f;
#pragma unroll 8
    for (int e = 0; e < Dd; e++) acc += q[e] * krow[e];
    __nv_bfloat16 b = __float2bfloat16_rn(acc);
    ((unsigned short*)g_Mt)[n * Dd + k] = *reinterpret_cast<const unsigned short*>(&b);
}

// ---------------------------------------------------------------------------
// Kernel 1b: fold Wv into W1 hist rows.  grid (16,16): block = 16 d x 64 h.
// ---------------------------------------------------------------------------
__global__ void __launch_bounds__(256) k_fold(const float* __restrict__ W1,
                                              const float* __restrict__ Wv) {
    __shared__ float wv[16 * 256];
    const int bd = blockIdx.x, bh = blockIdx.y;
    const int tid = threadIdx.x;
    for (int idx = tid; idx < 16 * 256; idx += 256)
        wv[idx] = Wv[(16 * bd + (idx >> 8)) * Dd + (idx & 255)];
    __syncthreads();
    const int hl = tid & 63, dg = tid >> 6;
    const int h = 64 * bh + hl;
    float acc[4] = {0.f, 0.f, 0.f, 0.f};
    for (int e = 0; e < 256; e++) {
        float w1v = W1[(DEMOd + e) * HIDd + h];
#pragma unroll
        for (int k2 = 0; k2 < 4; k2++)
            acc[k2] += wv[(dg * 4 + k2) * 256 + e] * w1v;
    }
#pragma unroll
    for (int k2 = 0; k2 < 4; k2++)
        g_W1f[(DEMOd + 16 * bd + dg * 4 + k2) * HIDd + h] = acc[k2];
}

// Kernel 1c: copy W1 demo rows into g_W1f.  grid 70.
__global__ void __launch_bounds__(256) k_cpy(const float* __restrict__ W1) {
    int r = blockIdx.x;
    for (int i = threadIdx.x; i < HIDd; i += 256)
        g_W1f[r * HIDd + i] = W1[r * HIDd + i];
}

// ---------------------------------------------------------------------------
// Kernel 2: HMMA fused attention, d'-chunked, S in registers. 2 CTAs/SM.
// ---------------------------------------------------------------------------
extern __shared__ char smem[];

__global__ void __launch_bounds__(512, 2) k_main(
    const float* __restrict__ E,
    const float* __restrict__ c_attn, const float* __restrict__ c_pool,
    const float* __restrict__ hist_times, const float* __restrict__ event_time,
    const int* __restrict__ codes, const int* __restrict__ lengths)
{
    const int n    = blockIdx.x;
    const int tid  = threadIdx.x;
    const int wid  = tid >> 5;
    const int lane = tid & 31;
    const int g    = lane >> 2;
    const int t4   = lane & 3;
    const int len  = lengths[n];

    const int lrow = lane & 15;
    const int lcol = (lane >> 4) * 16;

    unsigned* emb_u = (unsigned*)(smem + OFF_EMB);
    unsigned* mch_u = (unsigned*)(smem + OFF_MCH);
    unsigned* tch_u = (unsigned*)(smem + OFF_TCH);
    float*    times = (float*)(smem + OFF_TIMES);
    float*    w_sh  = (float*)(smem + OFF_W);
    float*    a_sh  = (float*)(smem + OFF_A);
    float*    red_sh = (float*)(smem + OFF_RED);
    int*      codes_sh = (int*)(smem + OFF_CODES);

    if (tid < Ld) {
        codes_sh[tid] = codes[n * Ld + tid];
        times[tid]    = hist_times[n * Ld + tid];
    }
    __syncthreads();

    // ---- gather emb (all 128 rows) -> bf16 row-major [128][264]
    for (int idx = tid; idx < 128 * 32; idx += 512) {
        int l = idx >> 5, q = idx & 31;
        const float4* src = (const float4*)(E + (size_t)codes_sh[l] * Dd + q * 8);
        float4 f0 = src[0], f1 = src[1];
        uint4 o;
        o.x = pack2(f0.x, f0.y); o.y = pack2(f0.z, f0.w);
        o.z = pack2(f1.x, f1.y); o.w = pack2(f1.z, f1.w);
        *(uint4*)(emb_u + l * ESTR32 + q * 4) = o;
    }
    __syncthreads();

    const int nmt = (len + 15) >> 4;        // active 16-row m-tiles
    const int njq = (len + 31) >> 5;        // 32-col j groups
    const int nit2 = nmt * njq;             // <= 32

    // static GEMM2 slot assignment (2 slots/warp)
    float acc2[2][16];
    int mts2[2], jqs2[2];
#pragma unroll
    for (int s = 0; s < 2; s++) {
        mts2[s] = -1;
        int it = wid + 16 * s;
        if (it < nit2) {
            mts2[s] = (it / njq) * 16;
            jqs2[s] = it - (it / njq) * njq;
#pragma unroll
            for (int i = 0; i < 16; i++) acc2[s][i] = 0.f;
        }
    }

    const int nit1 = nmt * 2;

    // ---- d'-chunk loop: GEMM1 slice -> T-chunk -> GEMM2 accumulate
    for (int h = 0; h < 8; h++) {
        {
            const uint4* src = ((const uint4*)g_Mt) + h * 1024;
            for (int i = tid; i < 1024; i += 512) {
                int r = i >> 5, c4 = i & 31;
                *(uint4*)(mch_u + r * ESTR32 + c4 * 4) = src[i];
            }
        }
        __syncthreads();

        // GEMM1: Tchunk = EMB @ Mt[32h..]^T, scaled into log2 domain
        for (int it = wid; it < nit1; it += 16) {
            const int m0 = (it >> 1) * 16, ng = it & 1;
            const uint32_t aA = smaddr(emb_u) + (m0 + lrow) * ESTRB + lcol;
            const uint32_t aB = smaddr(mch_u) + (ng * 16 + lrow) * ESTRB + lcol;
            float acc[8];
#pragma unroll
            for (int i = 0; i < 8; i++) acc[i] = 0.f;
#pragma unroll 4
            for (int kt = 0; kt < 16; kt++) {
                unsigned a0, a1, a2, a3, p0, p1, p2, p3;
                ldsm4(a0, a1, a2, a3, aA + kt * 32);
                ldsm4(p0, p1, p2, p3, aB + kt * 32);
                mma16816(acc + 0, a0, a1, a2, a3, p0, p2);
                mma16816(acc + 4, a0, a1, a2, a3, p1, p3);
            }
#pragma unroll
            for (int nt = 0; nt < 2; nt++) {
                int col = ng * 8 + nt * 4 + t4;
                tch_u[(m0 + g) * TSTR32 + col] =
                    pack2(acc[4 * nt] * SSCALE, acc[4 * nt + 1] * SSCALE);
                tch_u[(m0 + g + 8) * TSTR32 + col] =
                    pack2(acc[4 * nt + 2] * SSCALE, acc[4 * nt + 3] * SSCALE);
            }
        }
        __syncthreads();

        // GEMM2: S += Tchunk @ emb[:, 32h:32h+32]^T
#pragma unroll
        for (int s = 0; s < 2; s++) {
            if (mts2[s] >= 0) {
                const uint32_t aA2 = smaddr(tch_u) + (mts2[s] + lrow) * TSTRB + lcol;
                const uint32_t eb  = smaddr(emb_u) + h * 64 + lcol;
#pragma unroll
                for (int kt2 = 0; kt2 < 2; kt2++) {
                    unsigned a0, a1, a2, a3;
                    ldsm4(a0, a1, a2, a3, aA2 + kt2 * 32);
#pragma unroll
                    for (int jg = 0; jg < 2; jg++) {
                        unsigned p0, p1, p2, p3;
                        ldsm4(p0, p1, p2, p3,
                              eb + (jqs2[s] * 32 + jg * 16 + lrow) * ESTRB + kt2 * 32);
                        mma16816(acc2[s] + 8 * jg + 0, a0, a1, a2, a3, p0, p2);
                        mma16816(acc2[s] + 8 * jg + 4, a0, a1, a2, a3, p1, p3);
                    }
                }
            }
        }
        __syncthreads();
    }

    // ---- write S (bf16, log2 domain) into region
    {
        unsigned* pp32 = (unsigned*)(smem + OFF_RGN);
#pragma unroll
        for (int s = 0; s < 2; s++) {
            if (mts2[s] >= 0) {
                const int m0 = mts2[s];
#pragma unroll
                for (int jt = 0; jt < 4; jt++) {
                    int col = jqs2[s] * 16 + jt * 4 + t4;
                    pp32[(m0 + g) * PSTR32 + col] =
                        pack2(acc2[s][4 * jt], acc2[s][4 * jt + 1]);
                    pp32[(m0 + g + 8) * PSTR32 + col] =
                        pack2(acc2[s][4 * jt + 2], acc2[s][4 * jt + 3]);
                }
            }
        }
    }
    __syncthreads();

    // ---- softmax in place: ex2.approx.f16x2 on score pairs
    {
        const float cb = c_attn[0] * 1.44269504f;
        unsigned* pp32 = (unsigned*)(smem + OFF_RGN);
        const int npass = (len + 63) >> 6;
        for (int p = 0; p < npass; p++) {
            const int r0 = p * 64 + wid * 4;
            if (r0 < len) {                 // warp-uniform
#pragma unroll
                for (int r = 0; r < 4; r++) {
                    int i = r0 + r;
                    if (i < len) {
                        float ti = times[i];
                        float ex[4]; float sum = 0.f;
#pragma unroll
                        for (int k = 0; k < 2; k++) {
                            ex[2 * k] = 0.f; ex[2 * k + 1] = 0.f;
                            if (64 * k < len) {         // warp-uniform
                                int c = 32 * k + lane;
                                int j0 = 2 * c;
                                unsigned sv = pp32[i * PSTR32 + c];
                                __nv_bfloat162 s2 =
                                    *reinterpret_cast<__nv_bfloat162*>(&sv);
                                float a0 = (j0 < len)
                                    ? __bfloat162float(s2.x) - cb * fabsf(ti - times[j0])
                                    : -100.f;
                                float a1 = (j0 + 1 < len)
                                    ? __bfloat162float(s2.y) - cb * fabsf(ti - times[j0 + 1])
                                    : -100.f;
                                float2 e2 = exp2_pair(a0, a1);
                                ex[2 * k] = e2.x; ex[2 * k + 1] = e2.y;
                                sum += e2.x + e2.y;
                            }
                        }
                        for (int o = 16; o; o >>= 1)
                            sum += __shfl_xor_sync(0xffffffffu, sum, o);
                        float inv = 1.f / sum;
#pragma unroll
                        for (int k = 0; k < 2; k++) {
                            if (64 * k < len) {
                                int c = 32 * k + lane;
                                pp32[i * PSTR32 + c] =
                                    pack2(ex[2 * k] * inv, ex[2 * k + 1] * inv);
                            }
                        }
                    }
                }
            }
        }
    }
    __syncthreads();

    // ---- phase 4: pooling -> a (split-4) -> u (split-2) -> g_repr
    {
        const float cp = c_pool[0];
        const float ev = event_time[n];
        if (tid < 32) {
            float s[4]; float mx = -1e30f;
#pragma unroll
            for (int k = 0; k < 4; k++) {
                int l = lane + 32 * k;
                s[k] = (l < len) ? -cp * (ev - times[l]) : -1e30f;
                mx = fmaxf(mx, s[k]);
            }
            for (int o = 16; o; o >>= 1) mx = fmaxf(mx, __shfl_xor_sync(0xffffffffu, mx, o));
            float ex[4]; float sum = 0.f;
#pragma unroll
            for (int k = 0; k < 4; k++) {
                int l = lane + 32 * k;
                ex[k] = (l < len) ? __expf(s[k] - mx) : 0.f;
                sum += ex[k];
            }
            for (int o = 16; o; o >>= 1) sum += __shfl_xor_sync(0xffffffffu, sum, o);
            float inv = 1.f / sum;
#pragma unroll
            for (int k = 0; k < 4; k++) {
                int l = lane + 32 * k;
                if (l < Ld) w_sh[l] = (l < len) ? ex[k] * inv : 0.f;
            }
        }
        __syncthreads();

        {   // a partials: (j, l-chunk q)
            int j = tid & 127, q = tid >> 7;
            float part = 0.f;
            if (j < len) {
                const unsigned short* pp = (const unsigned short*)(smem + OFF_RGN);
                int l0 = 32 * q, l1 = min(32 * q + 32, len);
                for (int l = l0; l < l1; l++)
                    part += w_sh[l] * bf2f(pp[l * PSTRH + j]);
            }
            red_sh[(q << 7) + j] = part;
        }
        __syncthreads();
        if (tid < 128) {
            int j = tid;
            a_sh[j] = (j < len)
                ? red_sh[j] + red_sh[128 + j] + red_sh[256 + j] + red_sh[384 + j]
                : 0.f;
        }
        __syncthreads();

        {   // u partials: (d, l-half)
            int d = tid & 255, h2 = tid >> 8;
            float part = 0.f;
            const unsigned short* eh = (const unsigned short*)(smem + OFF_EMB);
            int l0 = 64 * h2, l1 = min(64 * h2 + 64, len);
            for (int j = l0; j < l1; j++)
                part += a_sh[j] * bf2f(eh[j * ESTRH + d]);
            red_sh[tid] = part;
        }
        __syncthreads();
        if (tid < 256)
            g_repr[n * Dd + tid] = red_sh[tid] + red_sh[256 + tid];
    }
}

// ---------------------------------------------------------------------------
// Kernel 3: MLP on folded weights. grid=(128,2); partial -> g_part[y][n].
// ---------------------------------------------------------------------------
#define TILE 16
#define XF   (DEMOd + Dd)

__global__ void __launch_bounds__(512) k_mlp(
    const float* __restrict__ b1, const float* __restrict__ W2,
    const float* __restrict__ demo)
{
    __shared__ float x_s[XF * TILE];
    __shared__ float red[16 * TILE];
    const int n0 = blockIdx.x * TILE, tid = threadIdx.x;
    const int y = blockIdx.y;
    const int hid = y * 512 + tid;
    const int wid = tid >> 5, lane = tid & 31;

    for (int idx = tid; idx < XF * TILE; idx += 512) {
        int m = idx >> 4, s = idx & 15;
        x_s[idx] = (m < DEMOd) ? demo[(n0 + s) * DEMOd + m]
                               : g_repr[(n0 + s) * Dd + (m - DEMOd)];
    }
    __syncthreads();

    float h[TILE];
    {
        float b = b1[hid];
#pragma unroll
        for (int s = 0; s < TILE; s++) h[s] = b;
    }
#pragma unroll 2
    for (int m = 0; m < XF; m++) {
        float w1 = g_W1f[m * HIDd + hid];
        float4 x0 = ((const float4*)(x_s + m * TILE))[0];
        float4 x1 = ((const float4*)(x_s + m * TILE))[1];
        float4 x2 = ((const float4*)(x_s + m * TILE))[2];
        float4 x3 = ((const float4*)(x_s + m * TILE))[3];
        float xv[TILE] = {x0.x, x0.y, x0.z, x0.w, x1.x, x1.y, x1.z, x1.w,
                          x2.x, x2.y, x2.z, x2.w, x3.x, x3.y, x3.z, x3.w};
#pragma unroll
        for (int s = 0; s < TILE; s++) h[s] += w1 * xv[s];
    }

    float part[TILE];
    {
        float w2 = W2[hid];
#pragma unroll
        for (int s = 0; s < TILE; s++) part[s] = fmaxf(h[s], 0.f) * w2;
    }
#pragma unroll
    for (int s = 0; s < TILE; s++)
        for (int o = 16; o; o >>= 1)
            part[s] += __shfl_xor_sync(0xffffffffu, part[s], o);
    if (lane == 0)
#pragma unroll
        for (int s = 0; s < TILE; s++) red[wid * TILE + s] = part[s];
    __syncthreads();
    if (tid < TILE) {
        float z = 0.f;
#pragma unroll
        for (int w = 0; w < 16; w++) z += red[w * TILE + tid];
        g_part[y * Nn + n0 + tid] = z;
    }
}

// ---------------------------------------------------------------------------
// Kernel 4: BCE + deterministic reduce + regularization
// ---------------------------------------------------------------------------
__device__ __forceinline__ float log_sigmoid(float z) {
    return (z >= 0.f) ? -log1pf(expf(-z)) : z - log1pf(expf(z));
}

__global__ void __launch_bounds__(256) k_red(const float* __restrict__ c_attn,
                                             const float* __restrict__ c_pool,
                                             const float* __restrict__ b2,
                                             const float* __restrict__ labels,
                                             float* __restrict__ out)
{
    __shared__ float red[256];
    int tid = threadIdx.x;
    float s = 0.f;
    float bb = b2[0];
    for (int i = tid; i < Nn; i += 256) {
        float z = g_part[i] + g_part[Nn + i] + bb;
        float y = labels[i];
        s += -(2.0f * y * log_sigmoid(z) + (1.0f - y) * log_sigmoid(-z));
    }
    red[tid] = s;
    __syncthreads();
    for (int k = 128; k > 0; k >>= 1) {
        if (tid < k) red[tid] += red[tid + k];
        __syncthreads();
    }
    if (tid == 0)
        out[0] = red[0] / (float)Nn + c_attn[0] * c_attn[0] + c_pool[0] * c_pool[0];
}

// ---------------------------------------------------------------------------
extern "C" void kernel_launch(void* const* d_in, const int* in_sizes, int n_in,
                              void* d_out, int out_size)
{
    const float* E          = (const float*)d_in[0];
    const float* Wq         = (const float*)d_in[1];
    const float* Wk         = (const float*)d_in[2];
    const float* Wv         = (const float*)d_in[3];
    const float* c_attn     = (const float*)d_in[4];
    const float* c_pool     = (const float*)d_in[5];
    const float* W1         = (const float*)d_in[6];
    const float* b1         = (const float*)d_in[7];
    const float* W2         = (const float*)d_in[8];
    const float* b2         = (const float*)d_in[9];
    const float* demo       = (const float*)d_in[10];
    const float* hist_times = (const float*)d_in[11];
    const float* event_time = (const float*)d_in[12];
    const float* labels     = (const float*)d_in[13];
    const int*   codes      = (const int*)d_in[14];
    const int*   lengths    = (const int*)d_in[15];

    cudaFuncSetAttribute(k_main, cudaFuncAttributeMaxDynamicSharedMemorySize, SMEM_TOTAL);

    k_M   <<<Dd, 256>>>(Wq, Wk);
    k_fold<<<dim3(16, 16), 256>>>(W1, Wv);
    k_cpy <<<DEMOd, 256>>>(W1);
    k_main<<<Nn, 512, SMEM_TOTAL>>>(E, c_attn, c_pool, hist_times, event_time,
                                    codes, lengths);
    k_mlp <<<dim3(Nn / TILE, 2), 512>>>(b1, W2, demo);
    k_red <<<1, 256>>>(c_attn, c_pool, b2, labels, (float*)d_out);
}